// round 11
// baseline (speedup 1.0000x reference)
#include <cuda_runtime.h>
#include <cuda_bf16.h>
#include <cstdint>
#include <math.h>

#define NN    100000
#define N2    200000
#define NPAD  200064          // 3126 * 64
#define NTILE 3126
#define EE    1200000
#define E2    (2 * EE)
#define HH    64
#define EMBD  100
#define BB    4096
#define SCAN_B 782            // ceil(NPAD/256)

// ---------------- scratch (device globals; no allocation allowed) ----------
__device__ float g_ah[(size_t)NPAD * 128];     // per node: [agg(64) | h(64)]
__device__ float g_deg[NPAD];
__device__ int   g_cnt[NPAD];
__device__ int   g_rp [NPAD + 1];              // CSR row ptr (by target)
__device__ int   g_cur[NPAD];                  // fill cursor
__device__ int   g_csr[E2];                    // CSR src indices
__device__ int   g_bsum[SCAN_B];
__device__ int   g_boff[SCAN_B];
__device__ float g_Wf[2 * 64 * 192];           // Wm@Wih per layer (fp32)
__device__ float g_bf[2 * 192];                // bm@Wih per layer
__device__ __nv_bfloat16 g_Bhi[2 * 256 * 128]; // fused B hi, [N=256][K=128]
__device__ __nv_bfloat16 g_Blo[2 * 256 * 128]; // fused B lo
__device__ float g_cat[BB * 128];
__device__ float g_hid[BB * 64];
__device__ float g_loss;

// ---------------- helpers ---------------------------------------------------
__device__ __forceinline__ uint32_t smem_u32(const void* p) {
    uint32_t a;
    asm("{ .reg .u64 t; cvta.to.shared.u64 t, %1; cvt.u32.u64 %0, t; }" : "=r"(a) : "l"(p));
    return a;
}
__device__ __forceinline__ void ldsm4(uint32_t* r, uint32_t addr) {
    asm volatile("ldmatrix.sync.aligned.m8n8.x4.shared.b16 {%0,%1,%2,%3}, [%4];"
                 : "=r"(r[0]), "=r"(r[1]), "=r"(r[2]), "=r"(r[3]) : "r"(addr));
}
__device__ __forceinline__ void mma16816(float* d, const uint32_t* a,
                                         uint32_t b0, uint32_t b1) {
    asm volatile(
        "mma.sync.aligned.m16n8k16.row.col.f32.bf16.bf16.f32 "
        "{%0,%1,%2,%3},{%4,%5,%6,%7},{%8,%9},{%0,%1,%2,%3};"
        : "+f"(d[0]), "+f"(d[1]), "+f"(d[2]), "+f"(d[3])
        : "r"(a[0]), "r"(a[1]), "r"(a[2]), "r"(a[3]), "r"(b0), "r"(b1));
}

// ---------------- init: zero counts + loss ----------------------------------
__global__ void init_kernel()
{
    const int idx = blockIdx.x * 256 + threadIdx.x;
    if (idx < NPAD) g_cnt[idx] = 0;
    if (idx == 0) { g_loss = 0.0f; g_rp[NPAD] = E2; }
}

// ---------------- degree count ----------------------------------------------
__global__ void deg_kernel(const int* __restrict__ adj0, const int* __restrict__ adj1)
{
    const int e = blockIdx.x * 256 + threadIdx.x;
    if (e >= E2) return;
    const int tgt = (e < EE) ? adj0[2 * e + 1] : (adj1[2 * (e - EE) + 1] + NN);
    atomicAdd(&g_cnt[tgt], 1);
}

// ---------------- prefix scan (3 kernels) -----------------------------------
__global__ void scan1_kernel()     // per-block sums
{
    __shared__ int s[256];
    const int i = blockIdx.x * 256 + threadIdx.x;
    s[threadIdx.x] = (i < NPAD) ? g_cnt[i] : 0;
    __syncthreads();
    for (int st = 128; st > 0; st >>= 1) {
        if (threadIdx.x < st) s[threadIdx.x] += s[threadIdx.x + st];
        __syncthreads();
    }
    if (threadIdx.x == 0) g_bsum[blockIdx.x] = s[0];
}

__global__ void scan2_kernel()     // exclusive scan of block sums (parallel)
{
    __shared__ int s[1024];
    const int i = threadIdx.x;
    const int v = (i < SCAN_B) ? g_bsum[i] : 0;
    s[i] = v;
    __syncthreads();
    int val = v;
    for (int st = 1; st < 1024; st <<= 1) {
        const int add = (i >= st) ? s[i - st] : 0;
        __syncthreads();
        val += add;
        s[i] = val;
        __syncthreads();
    }
    if (i < SCAN_B) g_boff[i] = val - v;   // exclusive
}

__global__ void scan3_kernel()     // block exclusive scan + offset -> rp, cur, deg
{
    __shared__ int s[256];
    const int i = blockIdx.x * 256 + threadIdx.x;
    const int v = (i < NPAD) ? g_cnt[i] : 0;
    s[threadIdx.x] = v;
    __syncthreads();
    int val = v;
    for (int st = 1; st < 256; st <<= 1) {
        int add = (threadIdx.x >= st) ? s[threadIdx.x - st] : 0;
        __syncthreads();
        val += add;
        s[threadIdx.x] = val;
        __syncthreads();
    }
    if (i < NPAD) {
        const int excl = g_boff[blockIdx.x] + val - v;
        g_rp [i] = excl;
        g_cur[i] = excl;
        g_deg[i] = (float)v;
    }
}

// ---------------- CSR fill ---------------------------------------------------
__global__ void fill_kernel(const int* __restrict__ adj0, const int* __restrict__ adj1)
{
    const int e = blockIdx.x * 256 + threadIdx.x;
    if (e >= E2) return;
    int src, tgt;
    if (e < EE) {
        const int2 st = reinterpret_cast<const int2*>(adj0)[e];
        src = st.x;       tgt = st.y;
    } else {
        const int2 st = reinterpret_cast<const int2*>(adj1)[e - EE];
        src = st.x + NN;  tgt = st.y + NN;
    }
    const int pos = atomicAdd(&g_cur[tgt], 1);
    g_csr[pos] = src;
}

// ------------- fuse1: Wf = Wm@Wih, bf = bm@Wih ------------------------------
__global__ __launch_bounds__(192) void fuse1_kernel(
    const float* __restrict__ Wm0, const float* __restrict__ Wih0, const float* __restrict__ bm0,
    const float* __restrict__ Wm1, const float* __restrict__ Wih1, const float* __restrict__ bm1)
{
    const int k = blockIdx.x;           // 0..64 (64 => bias row)
    const int l = blockIdx.y;
    const int j = threadIdx.x;
    const float* Wm  = l ? Wm1  : Wm0;
    const float* Wih = l ? Wih1 : Wih0;
    const float* bm  = l ? bm1  : bm0;
    __shared__ float row[HH];
    if (j < HH) row[j] = (k < HH) ? Wm[k * HH + j] : bm[j];
    __syncthreads();
    float acc = 0.0f;
#pragma unroll
    for (int m = 0; m < HH; m++) acc = fmaf(row[m], Wih[m * 192 + j], acc);
    if (k < HH) g_Wf[l * HH * 192 + k * 192 + j] = acc;
    else        g_bf[l * 192 + j] = acc;
}

// ------------- fuse2: build fused B [128,256] -> bf16 hi/lo [256][128] ------
__global__ void fuse2_kernel(const float* __restrict__ Whh0, const float* __restrict__ Whh1)
{
    const int k = threadIdx.x;          // 0..127
    const int n = blockIdx.x;           // 0..255
    const int l = blockIdx.y;
    const float* Wf  = g_Wf + l * 64 * 192;
    const float* Whh = l ? Whh1 : Whh0;
    float v;
    if (n < 128)      v = (k < 64) ? Wf[k * 192 + n] : Whh[(k - 64) * 192 + n];
    else if (n < 192) v = (k < 64) ? Wf[k * 192 + n] : 0.0f;
    else              v = (k < 64) ? 0.0f            : Whh[(k - 64) * 192 + (n - 64)];
    const __nv_bfloat16 hi = __float2bfloat16(v);
    const __nv_bfloat16 lo = __float2bfloat16(v - __bfloat162float(hi));
    g_Bhi[l * 256 * 128 + n * 128 + k] = hi;
    g_Blo[l * 256 * 128 + n * 128 + k] = lo;
}

// -------- projection: h half of g_ah ----------------------------------------
__global__ __launch_bounds__(256) void proj_kernel(
    const float* __restrict__ emb,
    const int* __restrict__ ind0, const int* __restrict__ ind1,
    const float* __restrict__ Wp, const float* __restrict__ bp)
{
    const int j   = threadIdx.x & 63;
    const int grp = threadIdx.x >> 6;      // 0..3
    float wc[EMBD];
#pragma unroll
    for (int k = 0; k < EMBD; k++) wc[k] = Wp[k * HH + j];
    const float bj = bp[j];

    __shared__ __align__(16) float s_e[8][EMBD];
    const int ntiles = N2 / 8;             // 25000
    for (int tile = blockIdx.x; tile < ntiles; tile += gridDim.x) {
        const int nb = tile * 8;
        __syncthreads();
        for (int idx = threadIdx.x; idx < 8 * EMBD; idx += 256) {
            const int r = idx / EMBD, c = idx - r * EMBD;
            const int node = nb + r;
            const int row  = (node < NN) ? ind0[node] : ind1[node - NN];
            s_e[r][c] = emb[row * EMBD + c];
        }
        __syncthreads();
        const int n0 = nb + grp;
        const int n1 = n0 + 4;
        float a0 = bj, a1 = 0.0f, a2 = bj, a3 = 0.0f;
#pragma unroll
        for (int k = 0; k < 96; k += 8) {
            const float4 v = *reinterpret_cast<const float4*>(&s_e[grp][k]);
            const float4 w = *reinterpret_cast<const float4*>(&s_e[grp][k + 4]);
            const float4 u = *reinterpret_cast<const float4*>(&s_e[grp + 4][k]);
            const float4 x = *reinterpret_cast<const float4*>(&s_e[grp + 4][k + 4]);
            a0 = fmaf(v.x, wc[k + 0], a0);
            a2 = fmaf(u.x, wc[k + 0], a2);
            a1 = fmaf(v.y, wc[k + 1], a1);
            a3 = fmaf(u.y, wc[k + 1], a3);
            a0 = fmaf(v.z, wc[k + 2], a0);
            a2 = fmaf(u.z, wc[k + 2], a2);
            a1 = fmaf(v.w, wc[k + 3], a1);
            a3 = fmaf(u.w, wc[k + 3], a3);
            a0 = fmaf(w.x, wc[k + 4], a0);
            a2 = fmaf(x.x, wc[k + 4], a2);
            a1 = fmaf(w.y, wc[k + 5], a1);
            a3 = fmaf(x.y, wc[k + 5], a3);
            a0 = fmaf(w.z, wc[k + 6], a0);
            a2 = fmaf(x.z, wc[k + 6], a2);
            a1 = fmaf(w.w, wc[k + 7], a1);
            a3 = fmaf(x.w, wc[k + 7], a3);
        }
        {
            const float4 v = *reinterpret_cast<const float4*>(&s_e[grp][96]);
            const float4 u = *reinterpret_cast<const float4*>(&s_e[grp + 4][96]);
            a0 = fmaf(v.x, wc[96], a0);
            a2 = fmaf(u.x, wc[96], a2);
            a1 = fmaf(v.y, wc[97], a1);
            a3 = fmaf(u.y, wc[97], a3);
            a0 = fmaf(v.z, wc[98], a0);
            a2 = fmaf(u.z, wc[98], a2);
            a1 = fmaf(v.w, wc[99], a1);
            a3 = fmaf(u.w, wc[99], a3);
        }
        g_ah[(size_t)n0 * 128 + 64 + j] = a0 + a1;
        g_ah[(size_t)n1 * 128 + 64 + j] = a2 + a3;
    }
}

// ---- pull-mode aggregation: agg[node] = sum_{src in CSR[node]} h[src] ------
__global__ __launch_bounds__(256) void gsum_kernel()
{
    const int node = blockIdx.x * 16 + (threadIdx.x >> 4);
    const int q    = threadIdx.x & 15;
    if (node >= NPAD) return;
    const int s = g_rp[node];
    const int e = g_rp[node + 1];
    float4 a0 = make_float4(0, 0, 0, 0);
    float4 a1 = make_float4(0, 0, 0, 0);
    int i = s;
    for (; i + 1 < e; i += 2) {
        const int s0 = g_csr[i];
        const int s1 = g_csr[i + 1];
        const float4 v0 = *reinterpret_cast<const float4*>(g_ah + (size_t)s0 * 128 + 64 + q * 4);
        const float4 v1 = *reinterpret_cast<const float4*>(g_ah + (size_t)s1 * 128 + 64 + q * 4);
        a0.x += v0.x; a0.y += v0.y; a0.z += v0.z; a0.w += v0.w;
        a1.x += v1.x; a1.y += v1.y; a1.z += v1.z; a1.w += v1.w;
    }
    if (i < e) {
        const int s0 = g_csr[i];
        const float4 v0 = *reinterpret_cast<const float4*>(g_ah + (size_t)s0 * 128 + 64 + q * 4);
        a0.x += v0.x; a0.y += v0.y; a0.z += v0.z; a0.w += v0.w;
    }
    a0.x += a1.x; a0.y += a1.y; a0.z += a1.z; a0.w += a1.w;
    *reinterpret_cast<float4*>(g_ah + (size_t)node * 128 + q * 4) = a0;
}

// ------- persistent fused GEMM + GRU epilogue (mma.sync + ldmatrix) ---------
// B hi/lo + bias loaded ONCE per CTA; tiles processed grid-stride. (R8 exact)
#define SM_BIAS  0                       // 448 floats
#define SM_AHI   2048                    // 64 x 272B
#define SM_ALO   19456
#define SM_BHI   36864                   // 256 x 272B
#define SM_BLO   106496
#define SM_TOTAL 176128
#define GGRID    152

__global__ __launch_bounds__(256, 1) void gemm_gru_kernel(
    const float* __restrict__ bih, const float* __restrict__ bhh, int layer)
{
    extern __shared__ __align__(16) char smem[];
    const uint32_t sb  = smem_u32(smem);
    const int tid  = threadIdx.x;

    // ---- one-time staging: bias + B hi/lo ----
    if (tid < 64) {
        float* bias = reinterpret_cast<float*>(smem + SM_BIAS);
        const int j = tid;
        bias[j]       = bih[j]       + bhh[j];
        bias[64 + j]  = bih[64 + j]  + bhh[64 + j];
        bias[128 + j] = bih[128 + j];
        bias[192 + j] = bhh[128 + j];
        const float* bf = g_bf + layer * 192;
        bias[256 + j] = bf[j];
        bias[320 + j] = bf[64 + j];
        bias[384 + j] = bf[128 + j];
    }
    {
        const uint4* bh = reinterpret_cast<const uint4*>(g_Bhi + layer * 256 * 128);
        const uint4* bl = reinterpret_cast<const uint4*>(g_Blo + layer * 256 * 128);
        for (int c = tid; c < 4096; c += 256) {
            const int n = c >> 4;
            const uint32_t off = (uint32_t)n * 272 + (c & 15) * 16;
            *reinterpret_cast<uint4*>(smem + SM_BHI + off) = bh[c];
            *reinterpret_cast<uint4*>(smem + SM_BLO + off) = bl[c];
        }
    }

    const int lane = tid & 31;
    const int warp = tid >> 5;
    const int wm = warp & 1;
    const int wn = warp >> 1;
    const int lg = lane >> 3, lr = lane & 7;
    const int a_m = lr + (lg & 1) * 8;
    const int a_k = (lg >> 1) * 8;
    const int b_n = lr + (lg >> 1) * 8;
    const int b_k = (lg & 1) * 8;
    const float* bias = reinterpret_cast<const float*>(smem + SM_BIAS);
    const int g = lane >> 2, t = lane & 3;

    __syncthreads();

    for (int tile = blockIdx.x; tile < NTILE; tile += GGRID) {
        const int base = tile * 64;

        // A tile: fp32 -> hi/lo bf16, rows of 128 bf16 padded to 272B
        {
            const float4* ar = reinterpret_cast<const float4*>(g_ah + (size_t)base * 128);
            for (int c = tid; c < 2048; c += 256) {
                const float4 v = ar[c];
                const int m = c >> 5, k = (c & 31) << 2;
                __nv_bfloat16 h0 = __float2bfloat16(v.x);
                __nv_bfloat16 h1 = __float2bfloat16(v.y);
                __nv_bfloat16 h2 = __float2bfloat16(v.z);
                __nv_bfloat16 h3 = __float2bfloat16(v.w);
                __nv_bfloat16 l0 = __float2bfloat16(v.x - __bfloat162float(h0));
                __nv_bfloat16 l1 = __float2bfloat16(v.y - __bfloat162float(h1));
                __nv_bfloat16 l2 = __float2bfloat16(v.z - __bfloat162float(h2));
                __nv_bfloat16 l3 = __float2bfloat16(v.w - __bfloat162float(h3));
                uint2 hp, lp;
                hp.x = ((uint32_t)__bfloat16_as_ushort(h1) << 16) | __bfloat16_as_ushort(h0);
                hp.y = ((uint32_t)__bfloat16_as_ushort(h3) << 16) | __bfloat16_as_ushort(h2);
                lp.x = ((uint32_t)__bfloat16_as_ushort(l1) << 16) | __bfloat16_as_ushort(l0);
                lp.y = ((uint32_t)__bfloat16_as_ushort(l3) << 16) | __bfloat16_as_ushort(l2);
                const uint32_t off = (uint32_t)m * 272 + k * 2;
                *reinterpret_cast<uint2*>(smem + SM_AHI + off) = hp;
                *reinterpret_cast<uint2*>(smem + SM_ALO + off) = lp;
            }
        }
        __syncthreads();

        float d[2][4][2][4];
#pragma unroll
        for (int a = 0; a < 2; a++)
#pragma unroll
            for (int b = 0; b < 4; b++)
#pragma unroll
                for (int c = 0; c < 2; c++)
#pragma unroll
                    for (int e = 0; e < 4; e++) d[a][b][c][e] = 0.0f;

#pragma unroll
        for (int ks = 0; ks < 8; ks++) {
            const int k0 = ks * 16;
            uint32_t ahi[2][4], alo[2][4];
#pragma unroll
            for (int mt = 0; mt < 2; mt++) {
                const uint32_t ra = (uint32_t)(wm * 32 + mt * 16 + a_m) * 272 + (k0 + a_k) * 2;
                ldsm4(ahi[mt], sb + SM_AHI + ra);
                ldsm4(alo[mt], sb + SM_ALO + ra);
            }
#pragma unroll
            for (int gate = 0; gate < 4; gate++) {
                const uint32_t rb = (uint32_t)(gate * 64 + wn * 16 + b_n) * 272 + (k0 + b_k) * 2;
                uint32_t bhi[4], blo[4];
                ldsm4(bhi, sb + SM_BHI + rb);
                ldsm4(blo, sb + SM_BLO + rb);
#pragma unroll
                for (int mt = 0; mt < 2; mt++) {
#pragma unroll
                    for (int f = 0; f < 2; f++) {
                        mma16816(d[mt][gate][f], ahi[mt], bhi[f * 2], bhi[f * 2 + 1]);
                        mma16816(d[mt][gate][f], ahi[mt], blo[f * 2], blo[f * 2 + 1]);
                        mma16816(d[mt][gate][f], alo[mt], bhi[f * 2], bhi[f * 2 + 1]);
                    }
                }
            }
        }

        // -------- register-resident GRU epilogue --------
        float degv[2][2];
#pragma unroll
        for (int mt = 0; mt < 2; mt++)
#pragma unroll
            for (int rr = 0; rr < 2; rr++)
                degv[mt][rr] = g_deg[(size_t)base + wm * 32 + mt * 16 + rr * 8 + g];

#pragma unroll
        for (int f = 0; f < 2; f++) {
            const int c = wn * 16 + f * 8 + 2 * t;
            const float br0 = bias[c],       br1 = bias[c + 1];
            const float bz0 = bias[64 + c],  bz1 = bias[64 + c + 1];
            const float bg0 = bias[128 + c], bg1 = bias[128 + c + 1];
            const float bh0 = bias[192 + c], bh1 = bias[192 + c + 1];
            const float fr0 = bias[256 + c], fr1 = bias[256 + c + 1];
            const float fz0 = bias[320 + c], fz1 = bias[320 + c + 1];
            const float fg0 = bias[384 + c], fg1 = bias[384 + c + 1];
#pragma unroll
            for (int mt = 0; mt < 2; mt++) {
#pragma unroll
                for (int rr = 0; rr < 2; rr++) {
                    const size_t grow = (size_t)base + wm * 32 + mt * 16 + rr * 8 + g;
                    const float deg = degv[mt][rr];
                    const int idx = rr * 2;
                    const float2 hold = *reinterpret_cast<const float2*>(g_ah + grow * 128 + 64 + c);
                    const float r0 = 1.0f / (1.0f + __expf(-(d[mt][0][f][idx]     + br0 + deg * fr0)));
                    const float r1 = 1.0f / (1.0f + __expf(-(d[mt][0][f][idx + 1] + br1 + deg * fr1)));
                    const float z0 = 1.0f / (1.0f + __expf(-(d[mt][1][f][idx]     + bz0 + deg * fz0)));
                    const float z1 = 1.0f / (1.0f + __expf(-(d[mt][1][f][idx + 1] + bz1 + deg * fz1)));
                    const float ig0 = d[mt][2][f][idx]     + bg0 + deg * fg0;
                    const float ig1 = d[mt][2][f][idx + 1] + bg1 + deg * fg1;
                    const float hg0 = d[mt][3][f][idx]     + bh0;
                    const float hg1 = d[mt][3][f][idx + 1] + bh1;
                    float nx0 = ig0 + r0 * hg0;
                    float nx1 = ig1 + r1 * hg1;
                    nx0 = fminf(fmaxf(nx0, -15.0f), 15.0f);
                    nx1 = fminf(fmaxf(nx1, -15.0f), 15.0f);
                    const float e20 = __expf(-2.0f * nx0);
                    const float e21 = __expf(-2.0f * nx1);
                    const float n0 = (1.0f - e20) / (1.0f + e20);
                    const float n1 = (1.0f - e21) / (1.0f + e21);
                    float2 hn;
                    hn.x = (1.0f - z0) * n0 + z0 * hold.x;
                    hn.y = (1.0f - z1) * n1 + z1 * hold.y;
                    *reinterpret_cast<float2*>(g_ah + grow * 128 + 64 + c) = hn;
                }
            }
        }
        __syncthreads();   // guard A-smem overwrite next tile
    }
}

// ---------------- gather propagated nodes into concat buffer ---------------
__global__ void gather_kernel(const int* __restrict__ prop0,
                              const int* __restrict__ prop1)
{
    const int i = blockIdx.x * blockDim.x + threadIdx.x;
    if (i >= 2 * BB * HH) return;
    const int half = i / (BB * HH);
    const int r    = i - half * (BB * HH);
    const int b = r >> 6, j = r & 63;
    const int node = half ? (prop1[b] + NN) : prop0[b];
    g_cat[b * 128 + half * 64 + j] = g_ah[(size_t)node * 128 + 64 + j];
}

// ---------------- hidden = relu(cat @ W1 + b1) -----------------------------
__global__ __launch_bounds__(256) void hidden_kernel(
    const float* __restrict__ W1, const float* __restrict__ b1)
{
    const int j   = threadIdx.x & 63;
    const int grp = threadIdx.x >> 6;
    float wc[2 * HH];
#pragma unroll
    for (int k = 0; k < 2 * HH; k++) wc[k] = W1[k * HH + j];
    const float bj = b1[j];

    __shared__ __align__(16) float s_c[4][2 * HH];
    const int ntiles = BB / 4;
    for (int tile = blockIdx.x; tile < ntiles; tile += gridDim.x) {
        const int b = tile * 4 + grp;
        __syncthreads();
        s_c[grp][j]      = g_cat[b * 128 + j];
        s_c[grp][j + 64] = g_cat[b * 128 + j + 64];
        __syncthreads();
        float a0 = bj, a1 = 0.0f;
#pragma unroll
        for (int k = 0; k < 2 * HH; k += 8) {
            const float4 v = *reinterpret_cast<const float4*>(&s_c[grp][k]);
            const float4 w = *reinterpret_cast<const float4*>(&s_c[grp][k + 4]);
            a0 = fmaf(v.x, wc[k + 0], a0);
            a1 = fmaf(v.y, wc[k + 1], a1);
            a0 = fmaf(v.z, wc[k + 2], a0);
            a1 = fmaf(v.w, wc[k + 3], a1);
            a0 = fmaf(w.x, wc[k + 4], a0);
            a1 = fmaf(w.y, wc[k + 5], a1);
            a0 = fmaf(w.z, wc[k + 6], a0);
            a1 = fmaf(w.w, wc[k + 7], a1);
        }
        g_hid[b * HH + j] = fmaxf(a0 + a1, 0.0f);
    }
}

// ---------------- head: z, probs, loss -------------------------------------
__global__ void head_kernel(const float* __restrict__ W2, const float* __restrict__ b2,
                            const int* __restrict__ labels, float* __restrict__ out)
{
    const int warp = (blockIdx.x * blockDim.x + threadIdx.x) >> 5;
    const int lane = threadIdx.x & 31;
    if (warp >= BB) return;
    float acc = fmaf(g_hid[warp * HH + lane],      W2[lane],      0.0f);
    acc       = fmaf(g_hid[warp * HH + lane + 32], W2[lane + 32], acc);
#pragma unroll
    for (int s = 16; s; s >>= 1) acc += __shfl_xor_sync(0xffffffffu, acc, s);
    if (lane == 0) {
        const float z = acc + b2[0];
        out[warp] = 1.0f / (1.0f + __expf(-z));
        const float y = (float)labels[warp];
        const float t = (y > 0.5f) ? -z : z;
        const float sp = fmaxf(t, 0.0f) + log1pf(__expf(-fabsf(t)));
        atomicAdd(&g_loss, sp);
    }
}

__global__ void finalize_kernel(float* __restrict__ out)
{
    out[BB] = g_loss * (1.0f / (float)BB);
}

// ---------------------------------------------------------------------------
extern "C" void kernel_launch(void* const* d_in, const int* in_sizes, int n_in,
                              void* d_out, int out_size)
{
    const int*   emb_ind[2] = {(const int*)d_in[0],  (const int*)d_in[1]};
    const int*   adj[2]     = {(const int*)d_in[2],  (const int*)d_in[3]};
    const int*   prop[2]    = {(const int*)d_in[4],  (const int*)d_in[5]};
    const int*   labels     =  (const int*)d_in[6];
    const float* emb_table  =  (const float*)d_in[7];
    const float* Wp         =  (const float*)d_in[8];
    const float* bp         =  (const float*)d_in[9];
    const float* Wm[2]  = {(const float*)d_in[10], (const float*)d_in[16]};
    const float* bm[2]  = {(const float*)d_in[11], (const float*)d_in[17]};
    const float* Wih[2] = {(const float*)d_in[12], (const float*)d_in[18]};
    const float* Whh[2] = {(const float*)d_in[13], (const float*)d_in[19]};
    const float* bih[2] = {(const float*)d_in[14], (const float*)d_in[20]};
    const float* bhh[2] = {(const float*)d_in[15], (const float*)d_in[21]};
    const float* W1 = (const float*)d_in[22];
    const float* b1 = (const float*)d_in[23];
    const float* W2 = (const float*)d_in[24];
    const float* b2 = (const float*)d_in[25];
    float* out = (float*)d_out;

    static bool attr_set = false;
    if (!attr_set) {
        cudaFuncSetAttribute(gemm_gru_kernel,
                             cudaFuncAttributeMaxDynamicSharedMemorySize, SM_TOTAL);
        attr_set = true;
    }

    init_kernel<<<(NPAD + 255) / 256, 256>>>();
    deg_kernel<<<(E2 + 255) / 256, 256>>>(adj[0], adj[1]);
    scan1_kernel<<<SCAN_B, 256>>>();
    scan2_kernel<<<1, 1024>>>();
    scan3_kernel<<<SCAN_B, 256>>>();
    fill_kernel<<<(E2 + 255) / 256, 256>>>(adj[0], adj[1]);
    {
        dim3 fg(HH + 1, 2);
        fuse1_kernel<<<fg, 192>>>(Wm[0], Wih[0], bm[0], Wm[1], Wih[1], bm[1]);
    }
    {
        dim3 f2(256, 2);
        fuse2_kernel<<<f2, 128>>>(Whh[0], Whh[1]);
    }
    proj_kernel<<<2048, 256>>>(emb_table, emb_ind[0], emb_ind[1], Wp, bp);
    for (int l = 0; l < 2; l++) {
        for (int t = 0; t < 3; t++) {
            gsum_kernel<<<NPAD / 16, 256>>>();
            gemm_gru_kernel<<<GGRID, 256, SM_TOTAL>>>(bih[l], bhh[l], l);
        }
    }
    gather_kernel<<<(2 * BB * HH + 255) / 256, 256>>>(prop[0], prop[1]);
    hidden_kernel<<<512, 256>>>(W1, b1);
    head_kernel<<<(BB * 32 + 255) / 256, 256>>>(W2, b2, labels, out);
    finalize_kernel<<<1, 1>>>(out);
    (void)in_sizes; (void)n_in; (void)out_size;
}

// round 12
// speedup vs baseline: 1.1554x; 1.1554x over previous
#include <cuda_runtime.h>
#include <cuda_bf16.h>
#include <cstdint>
#include <math.h>

#define NN    100000
#define N2    200000
#define NPAD  200064          // 3126 * 64
#define NTILE 3126
#define EE    1200000
#define E2    (2 * EE)
#define HH    64
#define EMBD  100
#define BB    4096
#define SCAN_B 782            // ceil(NPAD/256)

// ---------------- scratch (device globals; no allocation allowed) ----------
__device__ __align__(16) float g_h0[(size_t)NPAD * 64];
__device__ __align__(16) float g_h1[(size_t)NPAD * 64];
__device__ float g_deg[NPAD];
__device__ int   g_cnt[NPAD];
__device__ int   g_rp [NPAD + 1];              // CSR row ptr (by target)
__device__ int   g_cur[NPAD];                  // fill cursor
__device__ int   g_csr[E2];                    // CSR src indices
__device__ int   g_bsum[SCAN_B];
__device__ int   g_boff[SCAN_B];
__device__ float g_Wf[2 * 64 * 192];           // Wm@Wih per layer (fp32)
__device__ float g_bf[2 * 192];                // bm@Wih per layer
__device__ __nv_bfloat16 g_Bhi[2 * 256 * 128]; // fused B hi, [N=256][K=128]
__device__ __nv_bfloat16 g_Blo[2 * 256 * 128]; // fused B lo
__device__ float g_cat[BB * 128];
__device__ float g_hid[BB * 64];
__device__ float g_loss;

// ---------------- helpers ---------------------------------------------------
__device__ __forceinline__ uint32_t smem_u32(const void* p) {
    uint32_t a;
    asm("{ .reg .u64 t; cvta.to.shared.u64 t, %1; cvt.u32.u64 %0, t; }" : "=r"(a) : "l"(p));
    return a;
}
__device__ __forceinline__ void ldsm4(uint32_t* r, uint32_t addr) {
    asm volatile("ldmatrix.sync.aligned.m8n8.x4.shared.b16 {%0,%1,%2,%3}, [%4];"
                 : "=r"(r[0]), "=r"(r[1]), "=r"(r[2]), "=r"(r[3]) : "r"(addr));
}
__device__ __forceinline__ void mma16816(float* d, const uint32_t* a,
                                         uint32_t b0, uint32_t b1) {
    asm volatile(
        "mma.sync.aligned.m16n8k16.row.col.f32.bf16.bf16.f32 "
        "{%0,%1,%2,%3},{%4,%5,%6,%7},{%8,%9},{%0,%1,%2,%3};"
        : "+f"(d[0]), "+f"(d[1]), "+f"(d[2]), "+f"(d[3])
        : "r"(a[0]), "r"(a[1]), "r"(a[2]), "r"(a[3]), "r"(b0), "r"(b1));
}
__device__ __forceinline__ void split2(float x, float y, uint32_t& hi, uint32_t& lo) {
    const __nv_bfloat16 hx = __float2bfloat16(x);
    const __nv_bfloat16 hy = __float2bfloat16(y);
    const __nv_bfloat16 lx = __float2bfloat16(x - __bfloat162float(hx));
    const __nv_bfloat16 ly = __float2bfloat16(y - __bfloat162float(hy));
    hi = ((uint32_t)__bfloat16_as_ushort(hy) << 16) | __bfloat16_as_ushort(hx);
    lo = ((uint32_t)__bfloat16_as_ushort(ly) << 16) | __bfloat16_as_ushort(lx);
}

// ---------------- init: zero counts + loss ----------------------------------
__global__ void init_kernel()
{
    const int idx = blockIdx.x * 256 + threadIdx.x;
    if (idx < NPAD) g_cnt[idx] = 0;
    if (idx == 0) { g_loss = 0.0f; g_rp[NPAD] = E2; }
}

// ---------------- degree count ----------------------------------------------
__global__ void deg_kernel(const int* __restrict__ adj0, const int* __restrict__ adj1)
{
    const int e = blockIdx.x * 256 + threadIdx.x;
    if (e >= E2) return;
    const int tgt = (e < EE) ? adj0[2 * e + 1] : (adj1[2 * (e - EE) + 1] + NN);
    atomicAdd(&g_cnt[tgt], 1);
}

// ---------------- prefix scan (3 kernels) -----------------------------------
__global__ void scan1_kernel()
{
    __shared__ int s[256];
    const int i = blockIdx.x * 256 + threadIdx.x;
    s[threadIdx.x] = (i < NPAD) ? g_cnt[i] : 0;
    __syncthreads();
    for (int st = 128; st > 0; st >>= 1) {
        if (threadIdx.x < st) s[threadIdx.x] += s[threadIdx.x + st];
        __syncthreads();
    }
    if (threadIdx.x == 0) g_bsum[blockIdx.x] = s[0];
}

__global__ void scan2_kernel()
{
    __shared__ int s[1024];
    const int i = threadIdx.x;
    const int v = (i < SCAN_B) ? g_bsum[i] : 0;
    s[i] = v;
    __syncthreads();
    int val = v;
    for (int st = 1; st < 1024; st <<= 1) {
        const int add = (i >= st) ? s[i - st] : 0;
        __syncthreads();
        val += add;
        s[i] = val;
        __syncthreads();
    }
    if (i < SCAN_B) g_boff[i] = val - v;
}

__global__ void scan3_kernel()
{
    __shared__ int s[256];
    const int i = blockIdx.x * 256 + threadIdx.x;
    const int v = (i < NPAD) ? g_cnt[i] : 0;
    s[threadIdx.x] = v;
    __syncthreads();
    int val = v;
    for (int st = 1; st < 256; st <<= 1) {
        int add = (threadIdx.x >= st) ? s[threadIdx.x - st] : 0;
        __syncthreads();
        val += add;
        s[threadIdx.x] = val;
        __syncthreads();
    }
    if (i < NPAD) {
        const int excl = g_boff[blockIdx.x] + val - v;
        g_rp [i] = excl;
        g_cur[i] = excl;
        g_deg[i] = (float)v;
    }
}

// ---------------- CSR fill ---------------------------------------------------
__global__ void fill_kernel(const int* __restrict__ adj0, const int* __restrict__ adj1)
{
    const int e = blockIdx.x * 256 + threadIdx.x;
    if (e >= E2) return;
    int src, tgt;
    if (e < EE) {
        const int2 st = reinterpret_cast<const int2*>(adj0)[e];
        src = st.x;       tgt = st.y;
    } else {
        const int2 st = reinterpret_cast<const int2*>(adj1)[e - EE];
        src = st.x + NN;  tgt = st.y + NN;
    }
    const int pos = atomicAdd(&g_cur[tgt], 1);
    g_csr[pos] = src;
}

// ------------- fuse1: Wf = Wm@Wih, bf = bm@Wih ------------------------------
__global__ __launch_bounds__(192) void fuse1_kernel(
    const float* __restrict__ Wm0, const float* __restrict__ Wih0, const float* __restrict__ bm0,
    const float* __restrict__ Wm1, const float* __restrict__ Wih1, const float* __restrict__ bm1)
{
    const int k = blockIdx.x;
    const int l = blockIdx.y;
    const int j = threadIdx.x;
    const float* Wm  = l ? Wm1  : Wm0;
    const float* Wih = l ? Wih1 : Wih0;
    const float* bm  = l ? bm1  : bm0;
    __shared__ float row[HH];
    if (j < HH) row[j] = (k < HH) ? Wm[k * HH + j] : bm[j];
    __syncthreads();
    float acc = 0.0f;
#pragma unroll
    for (int m = 0; m < HH; m++) acc = fmaf(row[m], Wih[m * 192 + j], acc);
    if (k < HH) g_Wf[l * HH * 192 + k * 192 + j] = acc;
    else        g_bf[l * 192 + j] = acc;
}

// ------------- fuse2: build fused B [128,256] -> bf16 hi/lo [256][128] ------
__global__ void fuse2_kernel(const float* __restrict__ Whh0, const float* __restrict__ Whh1)
{
    const int k = threadIdx.x;
    const int n = blockIdx.x;
    const int l = blockIdx.y;
    const float* Wf  = g_Wf + l * 64 * 192;
    const float* Whh = l ? Whh1 : Whh0;
    float v;
    if (n < 128)      v = (k < 64) ? Wf[k * 192 + n] : Whh[(k - 64) * 192 + n];
    else if (n < 192) v = (k < 64) ? Wf[k * 192 + n] : 0.0f;
    else              v = (k < 64) ? 0.0f            : Whh[(k - 64) * 192 + (n - 64)];
    const __nv_bfloat16 hi = __float2bfloat16(v);
    const __nv_bfloat16 lo = __float2bfloat16(v - __bfloat162float(hi));
    g_Bhi[l * 256 * 128 + n * 128 + k] = hi;
    g_Blo[l * 256 * 128 + n * 128 + k] = lo;
}

// -------- projection: writes g_h0 -------------------------------------------
__global__ __launch_bounds__(256) void proj_kernel(
    const float* __restrict__ emb,
    const int* __restrict__ ind0, const int* __restrict__ ind1,
    const float* __restrict__ Wp, const float* __restrict__ bp)
{
    const int j   = threadIdx.x & 63;
    const int grp = threadIdx.x >> 6;
    float wc[EMBD];
#pragma unroll
    for (int k = 0; k < EMBD; k++) wc[k] = Wp[k * HH + j];
    const float bj = bp[j];

    __shared__ __align__(16) float s_e[8][EMBD];
    const int ntiles = N2 / 8;
    for (int tile = blockIdx.x; tile < ntiles; tile += gridDim.x) {
        const int nb = tile * 8;
        __syncthreads();
        for (int idx = threadIdx.x; idx < 8 * EMBD; idx += 256) {
            const int r = idx / EMBD, c = idx - r * EMBD;
            const int node = nb + r;
            const int row  = (node < NN) ? ind0[node] : ind1[node - NN];
            s_e[r][c] = emb[row * EMBD + c];
        }
        __syncthreads();
        const int n0 = nb + grp;
        const int n1 = n0 + 4;
        float a0 = bj, a1 = 0.0f, a2 = bj, a3 = 0.0f;
#pragma unroll
        for (int k = 0; k < 96; k += 8) {
            const float4 v = *reinterpret_cast<const float4*>(&s_e[grp][k]);
            const float4 w = *reinterpret_cast<const float4*>(&s_e[grp][k + 4]);
            const float4 u = *reinterpret_cast<const float4*>(&s_e[grp + 4][k]);
            const float4 x = *reinterpret_cast<const float4*>(&s_e[grp + 4][k + 4]);
            a0 = fmaf(v.x, wc[k + 0], a0);
            a2 = fmaf(u.x, wc[k + 0], a2);
            a1 = fmaf(v.y, wc[k + 1], a1);
            a3 = fmaf(u.y, wc[k + 1], a3);
            a0 = fmaf(v.z, wc[k + 2], a0);
            a2 = fmaf(u.z, wc[k + 2], a2);
            a1 = fmaf(v.w, wc[k + 3], a1);
            a3 = fmaf(u.w, wc[k + 3], a3);
            a0 = fmaf(w.x, wc[k + 4], a0);
            a2 = fmaf(x.x, wc[k + 4], a2);
            a1 = fmaf(w.y, wc[k + 5], a1);
            a3 = fmaf(x.y, wc[k + 5], a3);
            a0 = fmaf(w.z, wc[k + 6], a0);
            a2 = fmaf(x.z, wc[k + 6], a2);
            a1 = fmaf(w.w, wc[k + 7], a1);
            a3 = fmaf(x.w, wc[k + 7], a3);
        }
        {
            const float4 v = *reinterpret_cast<const float4*>(&s_e[grp][96]);
            const float4 u = *reinterpret_cast<const float4*>(&s_e[grp + 4][96]);
            a0 = fmaf(v.x, wc[96], a0);
            a2 = fmaf(u.x, wc[96], a2);
            a1 = fmaf(v.y, wc[97], a1);
            a3 = fmaf(u.y, wc[97], a3);
            a0 = fmaf(v.z, wc[98], a0);
            a2 = fmaf(u.z, wc[98], a2);
            a1 = fmaf(v.w, wc[99], a1);
            a3 = fmaf(u.w, wc[99], a3);
        }
        g_h0[(size_t)n0 * 64 + j] = a0 + a1;
        g_h0[(size_t)n1 * 64 + j] = a2 + a3;
    }
}

// ------ fused: gather-sum + GEMM + GRU epilogue (h ping-pong) ---------------
#define SM_BIAS  0                       // 448 floats
#define SM_AHI   2048                    // 64 x 272B
#define SM_ALO   19456
#define SM_BHI   36864                   // 256 x 272B
#define SM_BLO   106496
#define SM_TOTAL 176128
#define GGRID    152

__global__ __launch_bounds__(256, 1) void gg2_kernel(
    const float* __restrict__ bih, const float* __restrict__ bhh, int layer, int pp)
{
    extern __shared__ __align__(16) char smem[];
    const uint32_t sb  = smem_u32(smem);
    const int tid  = threadIdx.x;
    const float* hin  = pp ? g_h1 : g_h0;
    float*       hout = pp ? g_h0 : g_h1;

    // ---- one-time staging: bias + B hi/lo ----
    if (tid < 64) {
        float* bias = reinterpret_cast<float*>(smem + SM_BIAS);
        const int j = tid;
        bias[j]       = bih[j]       + bhh[j];
        bias[64 + j]  = bih[64 + j]  + bhh[64 + j];
        bias[128 + j] = bih[128 + j];
        bias[192 + j] = bhh[128 + j];
        const float* bf = g_bf + layer * 192;
        bias[256 + j] = bf[j];
        bias[320 + j] = bf[64 + j];
        bias[384 + j] = bf[128 + j];
    }
    {
        const uint4* bh = reinterpret_cast<const uint4*>(g_Bhi + layer * 256 * 128);
        const uint4* bl = reinterpret_cast<const uint4*>(g_Blo + layer * 256 * 128);
        for (int c = tid; c < 4096; c += 256) {
            const int n = c >> 4;
            const uint32_t off = (uint32_t)n * 272 + (c & 15) * 16;
            *reinterpret_cast<uint4*>(smem + SM_BHI + off) = bh[c];
            *reinterpret_cast<uint4*>(smem + SM_BLO + off) = bl[c];
        }
    }

    const int lane = tid & 31;
    const int warp = tid >> 5;
    const int wm = warp & 1;
    const int wn = warp >> 1;
    const int lg = lane >> 3, lr = lane & 7;
    const int a_m = lr + (lg & 1) * 8;
    const int a_k = (lg >> 1) * 8;
    const int b_n = lr + (lg >> 1) * 8;
    const int b_k = (lg & 1) * 8;
    const float* bias = reinterpret_cast<const float*>(smem + SM_BIAS);
    const int g = lane >> 2, t = lane & 3;
    const int gm = tid >> 4;               // 0..15 (node group in gather pass)
    const int gq = tid & 15;               // quad within node

    __syncthreads();

    for (int tile = blockIdx.x; tile < NTILE; tile += GGRID) {
        const int base = tile * 64;

        // ---- gather agg (CSR pull) -> AHI/ALO cols k=0..63 ----
#pragma unroll
        for (int pass = 0; pass < 4; pass++) {
            const int m   = gm + pass * 16;            // node in tile
            const int row = base + m;
            const int s = g_rp[row];
            const int e = g_rp[row + 1];
            float4 a0 = make_float4(0, 0, 0, 0);
            float4 a1 = make_float4(0, 0, 0, 0);
            int i = s;
            for (; i + 1 < e; i += 2) {
                const int s0 = g_csr[i];
                const int s1 = g_csr[i + 1];
                const float4 v0 = *reinterpret_cast<const float4*>(hin + (size_t)s0 * 64 + gq * 4);
                const float4 v1 = *reinterpret_cast<const float4*>(hin + (size_t)s1 * 64 + gq * 4);
                a0.x += v0.x; a0.y += v0.y; a0.z += v0.z; a0.w += v0.w;
                a1.x += v1.x; a1.y += v1.y; a1.z += v1.z; a1.w += v1.w;
            }
            if (i < e) {
                const int s0 = g_csr[i];
                const float4 v0 = *reinterpret_cast<const float4*>(hin + (size_t)s0 * 64 + gq * 4);
                a0.x += v0.x; a0.y += v0.y; a0.z += v0.z; a0.w += v0.w;
            }
            a0.x += a1.x; a0.y += a1.y; a0.z += a1.z; a0.w += a1.w;
            uint2 hp, lp;
            split2(a0.x, a0.y, hp.x, lp.x);
            split2(a0.z, a0.w, hp.y, lp.y);
            const uint32_t off = (uint32_t)m * 272 + gq * 8;   // k = 4q
            *reinterpret_cast<uint2*>(smem + SM_AHI + off) = hp;
            *reinterpret_cast<uint2*>(smem + SM_ALO + off) = lp;
        }

        // ---- h tile -> AHI/ALO cols k=64..127 ----
#pragma unroll
        for (int u = 0; u < 4; u++) {
            const int c = tid + u * 256;               // 0..1023
            const int m = c >> 4, q = c & 15;
            const float4 v = *reinterpret_cast<const float4*>(hin + (size_t)(base + m) * 64 + q * 4);
            uint2 hp, lp;
            split2(v.x, v.y, hp.x, lp.x);
            split2(v.z, v.w, hp.y, lp.y);
            const uint32_t off = (uint32_t)m * 272 + 128 + q * 8;  // k = 64+4q
            *reinterpret_cast<uint2*>(smem + SM_AHI + off) = hp;
            *reinterpret_cast<uint2*>(smem + SM_ALO + off) = lp;
        }
        __syncthreads();

        float d[2][4][2][4];
#pragma unroll
        for (int a = 0; a < 2; a++)
#pragma unroll
            for (int b = 0; b < 4; b++)
#pragma unroll
                for (int c = 0; c < 2; c++)
#pragma unroll
                    for (int e = 0; e < 4; e++) d[a][b][c][e] = 0.0f;

#pragma unroll
        for (int ks = 0; ks < 8; ks++) {
            const int k0 = ks * 16;
            uint32_t ahi[2][4], alo[2][4];
#pragma unroll
            for (int mt = 0; mt < 2; mt++) {
                const uint32_t ra = (uint32_t)(wm * 32 + mt * 16 + a_m) * 272 + (k0 + a_k) * 2;
                ldsm4(ahi[mt], sb + SM_AHI + ra);
                ldsm4(alo[mt], sb + SM_ALO + ra);
            }
#pragma unroll
            for (int gate = 0; gate < 4; gate++) {
                const uint32_t rb = (uint32_t)(gate * 64 + wn * 16 + b_n) * 272 + (k0 + b_k) * 2;
                uint32_t bhi[4], blo[4];
                ldsm4(bhi, sb + SM_BHI + rb);
                ldsm4(blo, sb + SM_BLO + rb);
#pragma unroll
                for (int mt = 0; mt < 2; mt++) {
#pragma unroll
                    for (int f = 0; f < 2; f++) {
                        mma16816(d[mt][gate][f], ahi[mt], bhi[f * 2], bhi[f * 2 + 1]);
                        mma16816(d[mt][gate][f], ahi[mt], blo[f * 2], blo[f * 2 + 1]);
                        mma16816(d[mt][gate][f], alo[mt], bhi[f * 2], bhi[f * 2 + 1]);
                    }
                }
            }
        }

        // -------- register-resident GRU epilogue --------
        float degv[2][2];
#pragma unroll
        for (int mt = 0; mt < 2; mt++)
#pragma unroll
            for (int rr = 0; rr < 2; rr++)
                degv[mt][rr] = g_deg[(size_t)base + wm * 32 + mt * 16 + rr * 8 + g];

#pragma unroll
        for (int f = 0; f < 2; f++) {
            const int c = wn * 16 + f * 8 + 2 * t;
            const float br0 = bias[c],       br1 = bias[c + 1];
            const float bz0 = bias[64 + c],  bz1 = bias[64 + c + 1];
            const float bg0 = bias[128 + c], bg1 = bias[128 + c + 1];
            const float bh0 = bias[192 + c], bh1 = bias[192 + c + 1];
            const float fr0 = bias[256 + c], fr1 = bias[256 + c + 1];
            const float fz0 = bias[320 + c], fz1 = bias[320 + c + 1];
            const float fg0 = bias[384 + c], fg1 = bias[384 + c + 1];
#pragma unroll
            for (int mt = 0; mt < 2; mt++) {
#pragma unroll
                for (int rr = 0; rr < 2; rr++) {
                    const size_t grow = (size_t)base + wm * 32 + mt * 16 + rr * 8 + g;
                    const float deg = degv[mt][rr];
                    const int idx = rr * 2;
                    const float2 hold = *reinterpret_cast<const float2*>(hin + grow * 64 + c);
                    const float r0 = 1.0f / (1.0f + __expf(-(d[mt][0][f][idx]     + br0 + deg * fr0)));
                    const float r1 = 1.0f / (1.0f + __expf(-(d[mt][0][f][idx + 1] + br1 + deg * fr1)));
                    const float z0 = 1.0f / (1.0f + __expf(-(d[mt][1][f][idx]     + bz0 + deg * fz0)));
                    const float z1 = 1.0f / (1.0f + __expf(-(d[mt][1][f][idx + 1] + bz1 + deg * fz1)));
                    const float ig0 = d[mt][2][f][idx]     + bg0 + deg * fg0;
                    const float ig1 = d[mt][2][f][idx + 1] + bg1 + deg * fg1;
                    const float hg0 = d[mt][3][f][idx]     + bh0;
                    const float hg1 = d[mt][3][f][idx + 1] + bh1;
                    float nx0 = ig0 + r0 * hg0;
                    float nx1 = ig1 + r1 * hg1;
                    nx0 = fminf(fmaxf(nx0, -15.0f), 15.0f);
                    nx1 = fminf(fmaxf(nx1, -15.0f), 15.0f);
                    const float e20 = __expf(-2.0f * nx0);
                    const float e21 = __expf(-2.0f * nx1);
                    const float n0 = (1.0f - e20) / (1.0f + e20);
                    const float n1 = (1.0f - e21) / (1.0f + e21);
                    float2 hn;
                    hn.x = (1.0f - z0) * n0 + z0 * hold.x;
                    hn.y = (1.0f - z1) * n1 + z1 * hold.y;
                    *reinterpret_cast<float2*>(hout + grow * 64 + c) = hn;
                }
            }
        }
        __syncthreads();   // guard A-smem overwrite next tile
    }
}

// ---------------- gather propagated nodes into concat buffer ---------------
__global__ void gather_kernel(const int* __restrict__ prop0,
                              const int* __restrict__ prop1)
{
    const int i = blockIdx.x * blockDim.x + threadIdx.x;
    if (i >= 2 * BB * HH) return;
    const int half = i / (BB * HH);
    const int r    = i - half * (BB * HH);
    const int b = r >> 6, j = r & 63;
    const int node = half ? (prop1[b] + NN) : prop0[b];
    g_cat[b * 128 + half * 64 + j] = g_h0[(size_t)node * 64 + j];
}

// ---------------- hidden = relu(cat @ W1 + b1) -----------------------------
__global__ __launch_bounds__(256) void hidden_kernel(
    const float* __restrict__ W1, const float* __restrict__ b1)
{
    const int j   = threadIdx.x & 63;
    const int grp = threadIdx.x >> 6;
    float wc[2 * HH];
#pragma unroll
    for (int k = 0; k < 2 * HH; k++) wc[k] = W1[k * HH + j];
    const float bj = b1[j];

    __shared__ __align__(16) float s_c[4][2 * HH];
    const int ntiles = BB / 4;
    for (int tile = blockIdx.x; tile < ntiles; tile += gridDim.x) {
        const int b = tile * 4 + grp;
        __syncthreads();
        s_c[grp][j]      = g_cat[b * 128 + j];
        s_c[grp][j + 64] = g_cat[b * 128 + j + 64];
        __syncthreads();
        float a0 = bj, a1 = 0.0f;
#pragma unroll
        for (int k = 0; k < 2 * HH; k += 8) {
            const float4 v = *reinterpret_cast<const float4*>(&s_c[grp][k]);
            const float4 w = *reinterpret_cast<const float4*>(&s_c[grp][k + 4]);
            a0 = fmaf(v.x, wc[k + 0], a0);
            a1 = fmaf(v.y, wc[k + 1], a1);
            a0 = fmaf(v.z, wc[k + 2], a0);
            a1 = fmaf(v.w, wc[k + 3], a1);
            a0 = fmaf(w.x, wc[k + 4], a0);
            a1 = fmaf(w.y, wc[k + 5], a1);
            a0 = fmaf(w.z, wc[k + 6], a0);
            a1 = fmaf(w.w, wc[k + 7], a1);
        }
        g_hid[b * HH + j] = fmaxf(a0 + a1, 0.0f);
    }
}

// ---------------- head: z, probs, loss -------------------------------------
__global__ void head_kernel(const float* __restrict__ W2, const float* __restrict__ b2,
                            const int* __restrict__ labels, float* __restrict__ out)
{
    const int warp = (blockIdx.x * blockDim.x + threadIdx.x) >> 5;
    const int lane = threadIdx.x & 31;
    if (warp >= BB) return;
    float acc = fmaf(g_hid[warp * HH + lane],      W2[lane],      0.0f);
    acc       = fmaf(g_hid[warp * HH + lane + 32], W2[lane + 32], acc);
#pragma unroll
    for (int s = 16; s; s >>= 1) acc += __shfl_xor_sync(0xffffffffu, acc, s);
    if (lane == 0) {
        const float z = acc + b2[0];
        out[warp] = 1.0f / (1.0f + __expf(-z));
        const float y = (float)labels[warp];
        const float t = (y > 0.5f) ? -z : z;
        const float sp = fmaxf(t, 0.0f) + log1pf(__expf(-fabsf(t)));
        atomicAdd(&g_loss, sp);
    }
}

__global__ void finalize_kernel(float* __restrict__ out)
{
    out[BB] = g_loss * (1.0f / (float)BB);
}

// ---------------------------------------------------------------------------
extern "C" void kernel_launch(void* const* d_in, const int* in_sizes, int n_in,
                              void* d_out, int out_size)
{
    const int*   emb_ind[2] = {(const int*)d_in[0],  (const int*)d_in[1]};
    const int*   adj[2]     = {(const int*)d_in[2],  (const int*)d_in[3]};
    const int*   prop[2]    = {(const int*)d_in[4],  (const int*)d_in[5]};
    const int*   labels     =  (const int*)d_in[6];
    const float* emb_table  =  (const float*)d_in[7];
    const float* Wp         =  (const float*)d_in[8];
    const float* bp         =  (const float*)d_in[9];
    const float* Wm[2]  = {(const float*)d_in[10], (const float*)d_in[16]};
    const float* bm[2]  = {(const float*)d_in[11], (const float*)d_in[17]};
    const float* Wih[2] = {(const float*)d_in[12], (const float*)d_in[18]};
    const float* Whh[2] = {(const float*)d_in[13], (const float*)d_in[19]};
    const float* bih[2] = {(const float*)d_in[14], (const float*)d_in[20]};
    const float* bhh[2] = {(const float*)d_in[15], (const float*)d_in[21]};
    const float* W1 = (const float*)d_in[22];
    const float* b1 = (const float*)d_in[23];
    const float* W2 = (const float*)d_in[24];
    const float* b2 = (const float*)d_in[25];
    float* out = (float*)d_out;

    static bool attr_set = false;
    if (!attr_set) {
        cudaFuncSetAttribute(gg2_kernel,
                             cudaFuncAttributeMaxDynamicSharedMemorySize, SM_TOTAL);
        attr_set = true;
    }

    init_kernel<<<(NPAD + 255) / 256, 256>>>();
    deg_kernel<<<(E2 + 255) / 256, 256>>>(adj[0], adj[1]);
    scan1_kernel<<<SCAN_B, 256>>>();
    scan2_kernel<<<1, 1024>>>();
    scan3_kernel<<<SCAN_B, 256>>>();
    fill_kernel<<<(E2 + 255) / 256, 256>>>(adj[0], adj[1]);
    {
        dim3 fg(HH + 1, 2);
        fuse1_kernel<<<fg, 192>>>(Wm[0], Wih[0], bm[0], Wm[1], Wih[1], bm[1]);
    }
    {
        dim3 f2(256, 2);
        fuse2_kernel<<<f2, 128>>>(Whh[0], Whh[1]);
    }
    proj_kernel<<<2048, 256>>>(emb_table, emb_ind[0], emb_ind[1], Wp, bp);
    int step = 0;
    for (int l = 0; l < 2; l++) {
        for (int t = 0; t < 3; t++) {
            gg2_kernel<<<GGRID, 256, SM_TOTAL>>>(bih[l], bhh[l], l, step & 1);
            step++;
        }
    }
    gather_kernel<<<(2 * BB * HH + 255) / 256, 256>>>(prop[0], prop[1]);
    hidden_kernel<<<512, 256>>>(W1, b1);
    head_kernel<<<(BB * 32 + 255) / 256, 256>>>(W2, b2, labels, out);
    finalize_kernel<<<1, 1>>>(out);
    (void)in_sizes; (void)n_in; (void)out_size;
}

// round 13
// speedup vs baseline: 1.2275x; 1.0624x over previous
#include <cuda_runtime.h>
#include <cuda_bf16.h>
#include <cstdint>
#include <math.h>

#define NN    100000
#define N2    200000
#define NPAD  200064          // 3126 * 64
#define NTILE 3126
#define EE    1200000
#define E2    (2 * EE)
#define HH    64
#define EMBD  100
#define BB    4096
#define SCAN_B 782            // ceil(NPAD/256)

// ---------------- scratch (device globals; no allocation allowed) ----------
__device__ __align__(16) float g_h0[(size_t)NPAD * 64];
__device__ __align__(16) float g_h1[(size_t)NPAD * 64];
__device__ float g_deg[NPAD];
__device__ int   g_cnt[NPAD];
__device__ int   g_rp [NPAD + 1];              // CSR row ptr (by target)
__device__ int   g_cur[NPAD];                  // fill cursor
__device__ int   g_csr[E2];                    // CSR src indices
__device__ int   g_bsum[SCAN_B];
__device__ int   g_boff[SCAN_B];
__device__ float g_Wf[2 * 64 * 192];           // Wm@Wih per layer (fp32)
__device__ float g_bf[2 * 192];                // bm@Wih per layer
__device__ __nv_bfloat16 g_Bhi[2 * 256 * 128]; // fused B hi, [N=256][K=128]
__device__ __nv_bfloat16 g_Blo[2 * 256 * 128]; // fused B lo
__device__ float g_cat[BB * 128];
__device__ float g_hid[BB * 64];
__device__ float g_loss;

// ---------------- helpers ---------------------------------------------------
__device__ __forceinline__ uint32_t smem_u32(const void* p) {
    uint32_t a;
    asm("{ .reg .u64 t; cvta.to.shared.u64 t, %1; cvt.u32.u64 %0, t; }" : "=r"(a) : "l"(p));
    return a;
}
__device__ __forceinline__ void ldsm4(uint32_t* r, uint32_t addr) {
    asm volatile("ldmatrix.sync.aligned.m8n8.x4.shared.b16 {%0,%1,%2,%3}, [%4];"
                 : "=r"(r[0]), "=r"(r[1]), "=r"(r[2]), "=r"(r[3]) : "r"(addr));
}
__device__ __forceinline__ void mma16816(float* d, const uint32_t* a,
                                         uint32_t b0, uint32_t b1) {
    asm volatile(
        "mma.sync.aligned.m16n8k16.row.col.f32.bf16.bf16.f32 "
        "{%0,%1,%2,%3},{%4,%5,%6,%7},{%8,%9},{%0,%1,%2,%3};"
        : "+f"(d[0]), "+f"(d[1]), "+f"(d[2]), "+f"(d[3])
        : "r"(a[0]), "r"(a[1]), "r"(a[2]), "r"(a[3]), "r"(b0), "r"(b1));
}
__device__ __forceinline__ void split2(float x, float y, uint32_t& hi, uint32_t& lo) {
    const __nv_bfloat16 hx = __float2bfloat16(x);
    const __nv_bfloat16 hy = __float2bfloat16(y);
    const __nv_bfloat16 lx = __float2bfloat16(x - __bfloat162float(hx));
    const __nv_bfloat16 ly = __float2bfloat16(y - __bfloat162float(hy));
    hi = ((uint32_t)__bfloat16_as_ushort(hy) << 16) | __bfloat16_as_ushort(hx);
    lo = ((uint32_t)__bfloat16_as_ushort(ly) << 16) | __bfloat16_as_ushort(lx);
}

// ---------------- init: zero counts + loss ----------------------------------
__global__ void init_kernel()
{
    const int idx = blockIdx.x * 256 + threadIdx.x;
    if (idx < NPAD) g_cnt[idx] = 0;
    if (idx == 0) { g_loss = 0.0f; g_rp[NPAD] = E2; }
}

// ---------------- degree count ----------------------------------------------
__global__ void deg_kernel(const int* __restrict__ adj0, const int* __restrict__ adj1)
{
    const int e = blockIdx.x * 256 + threadIdx.x;
    if (e >= E2) return;
    const int tgt = (e < EE) ? adj0[2 * e + 1] : (adj1[2 * (e - EE) + 1] + NN);
    atomicAdd(&g_cnt[tgt], 1);
}

// ---------------- prefix scan (3 kernels) -----------------------------------
__global__ void scan1_kernel()
{
    __shared__ int s[256];
    const int i = blockIdx.x * 256 + threadIdx.x;
    s[threadIdx.x] = (i < NPAD) ? g_cnt[i] : 0;
    __syncthreads();
    for (int st = 128; st > 0; st >>= 1) {
        if (threadIdx.x < st) s[threadIdx.x] += s[threadIdx.x + st];
        __syncthreads();
    }
    if (threadIdx.x == 0) g_bsum[blockIdx.x] = s[0];
}

__global__ void scan2_kernel()
{
    __shared__ int s[1024];
    const int i = threadIdx.x;
    const int v = (i < SCAN_B) ? g_bsum[i] : 0;
    s[i] = v;
    __syncthreads();
    int val = v;
    for (int st = 1; st < 1024; st <<= 1) {
        const int add = (i >= st) ? s[i - st] : 0;
        __syncthreads();
        val += add;
        s[i] = val;
        __syncthreads();
    }
    if (i < SCAN_B) g_boff[i] = val - v;
}

__global__ void scan3_kernel()
{
    __shared__ int s[256];
    const int i = blockIdx.x * 256 + threadIdx.x;
    const int v = (i < NPAD) ? g_cnt[i] : 0;
    s[threadIdx.x] = v;
    __syncthreads();
    int val = v;
    for (int st = 1; st < 256; st <<= 1) {
        int add = (threadIdx.x >= st) ? s[threadIdx.x - st] : 0;
        __syncthreads();
        val += add;
        s[threadIdx.x] = val;
        __syncthreads();
    }
    if (i < NPAD) {
        const int excl = g_boff[blockIdx.x] + val - v;
        g_rp [i] = excl;
        g_cur[i] = excl;
        g_deg[i] = (float)v;
    }
}

// ---------------- CSR fill ---------------------------------------------------
__global__ void fill_kernel(const int* __restrict__ adj0, const int* __restrict__ adj1)
{
    const int e = blockIdx.x * 256 + threadIdx.x;
    if (e >= E2) return;
    int src, tgt;
    if (e < EE) {
        const int2 st = reinterpret_cast<const int2*>(adj0)[e];
        src = st.x;       tgt = st.y;
    } else {
        const int2 st = reinterpret_cast<const int2*>(adj1)[e - EE];
        src = st.x + NN;  tgt = st.y + NN;
    }
    const int pos = atomicAdd(&g_cur[tgt], 1);
    g_csr[pos] = src;
}

// ------------- fuse1: Wf = Wm@Wih, bf = bm@Wih ------------------------------
__global__ __launch_bounds__(192) void fuse1_kernel(
    const float* __restrict__ Wm0, const float* __restrict__ Wih0, const float* __restrict__ bm0,
    const float* __restrict__ Wm1, const float* __restrict__ Wih1, const float* __restrict__ bm1)
{
    const int k = blockIdx.x;
    const int l = blockIdx.y;
    const int j = threadIdx.x;
    const float* Wm  = l ? Wm1  : Wm0;
    const float* Wih = l ? Wih1 : Wih0;
    const float* bm  = l ? bm1  : bm0;
    __shared__ float row[HH];
    if (j < HH) row[j] = (k < HH) ? Wm[k * HH + j] : bm[j];
    __syncthreads();
    float acc = 0.0f;
#pragma unroll
    for (int m = 0; m < HH; m++) acc = fmaf(row[m], Wih[m * 192 + j], acc);
    if (k < HH) g_Wf[l * HH * 192 + k * 192 + j] = acc;
    else        g_bf[l * 192 + j] = acc;
}

// ------------- fuse2: build fused B [128,256] -> bf16 hi/lo [256][128] ------
__global__ void fuse2_kernel(const float* __restrict__ Whh0, const float* __restrict__ Whh1)
{
    const int k = threadIdx.x;
    const int n = blockIdx.x;
    const int l = blockIdx.y;
    const float* Wf  = g_Wf + l * 64 * 192;
    const float* Whh = l ? Whh1 : Whh0;
    float v;
    if (n < 128)      v = (k < 64) ? Wf[k * 192 + n] : Whh[(k - 64) * 192 + n];
    else if (n < 192) v = (k < 64) ? Wf[k * 192 + n] : 0.0f;
    else              v = (k < 64) ? 0.0f            : Whh[(k - 64) * 192 + (n - 64)];
    const __nv_bfloat16 hi = __float2bfloat16(v);
    const __nv_bfloat16 lo = __float2bfloat16(v - __bfloat162float(hi));
    g_Bhi[l * 256 * 128 + n * 128 + k] = hi;
    g_Blo[l * 256 * 128 + n * 128 + k] = lo;
}

// -------- projection via mma.sync: h0 = emb[ind] @ Wp + bp -------------------
// Per tile: A = [64 nodes x 128pad], B = Wp^T [64 x 128pad] -> D[64 x 64]
#define PSM_BIAS  0                       // 64 floats
#define PSM_AHI   512                     // 64 x 272B
#define PSM_ALO   17920
#define PSM_BHI   35328
#define PSM_BLO   52736
#define PSM_TOTAL 70144
#define GGRID     152

__global__ __launch_bounds__(256, 1) void proj_mma_kernel(
    const float* __restrict__ emb,
    const int* __restrict__ ind0, const int* __restrict__ ind1,
    const float* __restrict__ Wp, const float* __restrict__ bp)
{
    extern __shared__ __align__(16) char smem[];
    const uint32_t sb = smem_u32(smem);
    const int tid = threadIdx.x;

    // one-time: bias + B (= Wp^T) hi/lo + zero A padding cols k in [100,128)
    if (tid < 64) reinterpret_cast<float*>(smem + PSM_BIAS)[tid] = bp[tid];
    for (int c = tid; c < 64 * 128; c += 256) {
        const int n = c >> 7, k = c & 127;
        const float v = (k < EMBD) ? Wp[k * 64 + n] : 0.0f;
        const __nv_bfloat16 hi = __float2bfloat16(v);
        const __nv_bfloat16 lo = __float2bfloat16(v - __bfloat162float(hi));
        *reinterpret_cast<__nv_bfloat16*>(smem + PSM_BHI + n * 272 + k * 2) = hi;
        *reinterpret_cast<__nv_bfloat16*>(smem + PSM_BLO + n * 272 + k * 2) = lo;
    }
    for (int c = tid; c < 64 * 14; c += 256) {       // bytes [200,256) per row
        const int m = c / 14, w = c - m * 14;
        *reinterpret_cast<uint32_t*>(smem + PSM_AHI + m * 272 + 200 + w * 4) = 0;
        *reinterpret_cast<uint32_t*>(smem + PSM_ALO + m * 272 + 200 + w * 4) = 0;
    }

    const int lane = tid & 31;
    const int warp = tid >> 5;
    const int wm = warp & 1;
    const int wn = warp >> 1;
    const int lg = lane >> 3, lr = lane & 7;
    const int a_m = lr + (lg & 1) * 8;
    const int a_k = (lg >> 1) * 8;
    const int b_n = lr + (lg >> 1) * 8;
    const int b_k = (lg & 1) * 8;
    const float* bias = reinterpret_cast<const float*>(smem + PSM_BIAS);
    const int g = lane >> 2, t = lane & 3;
    const int gm = tid >> 2;              // 0..63: node in tile (gather phase)
    const int gq = tid & 3;               // 4 threads per node

    __syncthreads();

    for (int tile = blockIdx.x; tile < NTILE; tile += GGRID) {
        const int base = tile * 64;

        // gather emb rows -> AHI/ALO (k = 0..99)
        {
            const int node = base + gm;
            const int row  = (node < NN) ? ind0[node] : ind1[node - NN];
            const float* er = emb + (size_t)row * EMBD;
#pragma unroll
            for (int i = gq; i < 25; i += 4) {        // float4 index
                const float4 v = *reinterpret_cast<const float4*>(er + i * 4);
                uint2 hp, lp;
                split2(v.x, v.y, hp.x, lp.x);
                split2(v.z, v.w, hp.y, lp.y);
                const uint32_t off = (uint32_t)gm * 272 + i * 8;
                *reinterpret_cast<uint2*>(smem + PSM_AHI + off) = hp;
                *reinterpret_cast<uint2*>(smem + PSM_ALO + off) = lp;
            }
        }
        __syncthreads();

        float d[2][2][4];                  // [mt][f][frag]
#pragma unroll
        for (int a = 0; a < 2; a++)
#pragma unroll
            for (int b = 0; b < 2; b++)
#pragma unroll
                for (int c = 0; c < 4; c++) d[a][b][c] = 0.0f;

#pragma unroll
        for (int ks = 0; ks < 8; ks++) {
            const int k0 = ks * 16;
            uint32_t ahi[2][4], alo[2][4];
#pragma unroll
            for (int mt = 0; mt < 2; mt++) {
                const uint32_t ra = (uint32_t)(wm * 32 + mt * 16 + a_m) * 272 + (k0 + a_k) * 2;
                ldsm4(ahi[mt], sb + PSM_AHI + ra);
                ldsm4(alo[mt], sb + PSM_ALO + ra);
            }
            const uint32_t rb = (uint32_t)(wn * 16 + b_n) * 272 + (k0 + b_k) * 2;
            uint32_t bhi[4], blo[4];
            ldsm4(bhi, sb + PSM_BHI + rb);
            ldsm4(blo, sb + PSM_BLO + rb);
#pragma unroll
            for (int mt = 0; mt < 2; mt++) {
#pragma unroll
                for (int f = 0; f < 2; f++) {
                    mma16816(d[mt][f], ahi[mt], bhi[f * 2], bhi[f * 2 + 1]);
                    mma16816(d[mt][f], ahi[mt], blo[f * 2], blo[f * 2 + 1]);
                    mma16816(d[mt][f], alo[mt], bhi[f * 2], bhi[f * 2 + 1]);
                }
            }
        }

        // epilogue: + bias -> g_h0
#pragma unroll
        for (int f = 0; f < 2; f++) {
            const int c = wn * 16 + f * 8 + 2 * t;
            const float b0 = bias[c], b1 = bias[c + 1];
#pragma unroll
            for (int mt = 0; mt < 2; mt++) {
#pragma unroll
                for (int rr = 0; rr < 2; rr++) {
                    const size_t grow = (size_t)base + wm * 32 + mt * 16 + rr * 8 + g;
                    const int idx = rr * 2;
                    *reinterpret_cast<float2*>(g_h0 + grow * 64 + c) =
                        make_float2(d[mt][f][idx] + b0, d[mt][f][idx + 1] + b1);
                }
            }
        }
        __syncthreads();
    }
}

// ------ fused: gather-sum + GEMM + GRU epilogue (h ping-pong) ---------------
#define SM_BIAS  0                       // 448 floats
#define SM_AHI   2048                    // 64 x 272B
#define SM_ALO   19456
#define SM_BHI   36864                   // 256 x 272B
#define SM_BLO   106496
#define SM_TOTAL 176128

__global__ __launch_bounds__(256, 1) void gg2_kernel(
    const float* __restrict__ bih, const float* __restrict__ bhh, int layer, int pp)
{
    extern __shared__ __align__(16) char smem[];
    const uint32_t sb  = smem_u32(smem);
    const int tid  = threadIdx.x;
    const float* hin  = pp ? g_h1 : g_h0;
    float*       hout = pp ? g_h0 : g_h1;

    if (tid < 64) {
        float* bias = reinterpret_cast<float*>(smem + SM_BIAS);
        const int j = tid;
        bias[j]       = bih[j]       + bhh[j];
        bias[64 + j]  = bih[64 + j]  + bhh[64 + j];
        bias[128 + j] = bih[128 + j];
        bias[192 + j] = bhh[128 + j];
        const float* bf = g_bf + layer * 192;
        bias[256 + j] = bf[j];
        bias[320 + j] = bf[64 + j];
        bias[384 + j] = bf[128 + j];
    }
    {
        const uint4* bh = reinterpret_cast<const uint4*>(g_Bhi + layer * 256 * 128);
        const uint4* bl = reinterpret_cast<const uint4*>(g_Blo + layer * 256 * 128);
        for (int c = tid; c < 4096; c += 256) {
            const int n = c >> 4;
            const uint32_t off = (uint32_t)n * 272 + (c & 15) * 16;
            *reinterpret_cast<uint4*>(smem + SM_BHI + off) = bh[c];
            *reinterpret_cast<uint4*>(smem + SM_BLO + off) = bl[c];
        }
    }

    const int lane = tid & 31;
    const int warp = tid >> 5;
    const int wm = warp & 1;
    const int wn = warp >> 1;
    const int lg = lane >> 3, lr = lane & 7;
    const int a_m = lr + (lg & 1) * 8;
    const int a_k = (lg >> 1) * 8;
    const int b_n = lr + (lg >> 1) * 8;
    const int b_k = (lg & 1) * 8;
    const float* bias = reinterpret_cast<const float*>(smem + SM_BIAS);
    const int g = lane >> 2, t = lane & 3;
    const int gm = tid >> 4;
    const int gq = tid & 15;

    __syncthreads();

    for (int tile = blockIdx.x; tile < NTILE; tile += GGRID) {
        const int base = tile * 64;

        // ---- gather agg (CSR pull) -> AHI/ALO cols k=0..63 ----
#pragma unroll
        for (int pass = 0; pass < 4; pass++) {
            const int m   = gm + pass * 16;
            const int row = base + m;
            const int s = g_rp[row];
            const int e = g_rp[row + 1];
            float4 a0 = make_float4(0, 0, 0, 0);
            float4 a1 = make_float4(0, 0, 0, 0);
            int i = s;
            for (; i + 1 < e; i += 2) {
                const int s0 = g_csr[i];
                const int s1 = g_csr[i + 1];
                const float4 v0 = *reinterpret_cast<const float4*>(hin + (size_t)s0 * 64 + gq * 4);
                const float4 v1 = *reinterpret_cast<const float4*>(hin + (size_t)s1 * 64 + gq * 4);
                a0.x += v0.x; a0.y += v0.y; a0.z += v0.z; a0.w += v0.w;
                a1.x += v1.x; a1.y += v1.y; a1.z += v1.z; a1.w += v1.w;
            }
            if (i < e) {
                const int s0 = g_csr[i];
                const float4 v0 = *reinterpret_cast<const float4*>(hin + (size_t)s0 * 64 + gq * 4);
                a0.x += v0.x; a0.y += v0.y; a0.z += v0.z; a0.w += v0.w;
            }
            a0.x += a1.x; a0.y += a1.y; a0.z += a1.z; a0.w += a1.w;
            uint2 hp, lp;
            split2(a0.x, a0.y, hp.x, lp.x);
            split2(a0.z, a0.w, hp.y, lp.y);
            const uint32_t off = (uint32_t)m * 272 + gq * 8;
            *reinterpret_cast<uint2*>(smem + SM_AHI + off) = hp;
            *reinterpret_cast<uint2*>(smem + SM_ALO + off) = lp;
        }

        // ---- h tile -> AHI/ALO cols k=64..127 ----
#pragma unroll
        for (int u = 0; u < 4; u++) {
            const int c = tid + u * 256;
            const int m = c >> 4, q = c & 15;
            const float4 v = *reinterpret_cast<const float4*>(hin + (size_t)(base + m) * 64 + q * 4);
            uint2 hp, lp;
            split2(v.x, v.y, hp.x, lp.x);
            split2(v.z, v.w, hp.y, lp.y);
            const uint32_t off = (uint32_t)m * 272 + 128 + q * 8;
            *reinterpret_cast<uint2*>(smem + SM_AHI + off) = hp;
            *reinterpret_cast<uint2*>(smem + SM_ALO + off) = lp;
        }
        __syncthreads();

        float d[2][4][2][4];
#pragma unroll
        for (int a = 0; a < 2; a++)
#pragma unroll
            for (int b = 0; b < 4; b++)
#pragma unroll
                for (int c = 0; c < 2; c++)
#pragma unroll
                    for (int e = 0; e < 4; e++) d[a][b][c][e] = 0.0f;

#pragma unroll
        for (int ks = 0; ks < 8; ks++) {
            const int k0 = ks * 16;
            uint32_t ahi[2][4], alo[2][4];
#pragma unroll
            for (int mt = 0; mt < 2; mt++) {
                const uint32_t ra = (uint32_t)(wm * 32 + mt * 16 + a_m) * 272 + (k0 + a_k) * 2;
                ldsm4(ahi[mt], sb + SM_AHI + ra);
                ldsm4(alo[mt], sb + SM_ALO + ra);
            }
#pragma unroll
            for (int gate = 0; gate < 4; gate++) {
                const uint32_t rb = (uint32_t)(gate * 64 + wn * 16 + b_n) * 272 + (k0 + b_k) * 2;
                uint32_t bhi[4], blo[4];
                ldsm4(bhi, sb + SM_BHI + rb);
                ldsm4(blo, sb + SM_BLO + rb);
#pragma unroll
                for (int mt = 0; mt < 2; mt++) {
#pragma unroll
                    for (int f = 0; f < 2; f++) {
                        mma16816(d[mt][gate][f], ahi[mt], bhi[f * 2], bhi[f * 2 + 1]);
                        mma16816(d[mt][gate][f], ahi[mt], blo[f * 2], blo[f * 2 + 1]);
                        mma16816(d[mt][gate][f], alo[mt], bhi[f * 2], bhi[f * 2 + 1]);
                    }
                }
            }
        }

        // -------- register-resident GRU epilogue --------
        float degv[2][2];
#pragma unroll
        for (int mt = 0; mt < 2; mt++)
#pragma unroll
            for (int rr = 0; rr < 2; rr++)
                degv[mt][rr] = g_deg[(size_t)base + wm * 32 + mt * 16 + rr * 8 + g];

#pragma unroll
        for (int f = 0; f < 2; f++) {
            const int c = wn * 16 + f * 8 + 2 * t;
            const float br0 = bias[c],       br1 = bias[c + 1];
            const float bz0 = bias[64 + c],  bz1 = bias[64 + c + 1];
            const float bg0 = bias[128 + c], bg1 = bias[128 + c + 1];
            const float bh0 = bias[192 + c], bh1 = bias[192 + c + 1];
            const float fr0 = bias[256 + c], fr1 = bias[256 + c + 1];
            const float fz0 = bias[320 + c], fz1 = bias[320 + c + 1];
            const float fg0 = bias[384 + c], fg1 = bias[384 + c + 1];
#pragma unroll
            for (int mt = 0; mt < 2; mt++) {
#pragma unroll
                for (int rr = 0; rr < 2; rr++) {
                    const size_t grow = (size_t)base + wm * 32 + mt * 16 + rr * 8 + g;
                    const float deg = degv[mt][rr];
                    const int idx = rr * 2;
                    const float2 hold = *reinterpret_cast<const float2*>(hin + grow * 64 + c);
                    const float r0 = 1.0f / (1.0f + __expf(-(d[mt][0][f][idx]     + br0 + deg * fr0)));
                    const float r1 = 1.0f / (1.0f + __expf(-(d[mt][0][f][idx + 1] + br1 + deg * fr1)));
                    const float z0 = 1.0f / (1.0f + __expf(-(d[mt][1][f][idx]     + bz0 + deg * fz0)));
                    const float z1 = 1.0f / (1.0f + __expf(-(d[mt][1][f][idx + 1] + bz1 + deg * fz1)));
                    const float ig0 = d[mt][2][f][idx]     + bg0 + deg * fg0;
                    const float ig1 = d[mt][2][f][idx + 1] + bg1 + deg * fg1;
                    const float hg0 = d[mt][3][f][idx]     + bh0;
                    const float hg1 = d[mt][3][f][idx + 1] + bh1;
                    float nx0 = ig0 + r0 * hg0;
                    float nx1 = ig1 + r1 * hg1;
                    nx0 = fminf(fmaxf(nx0, -15.0f), 15.0f);
                    nx1 = fminf(fmaxf(nx1, -15.0f), 15.0f);
                    const float e20 = __expf(-2.0f * nx0);
                    const float e21 = __expf(-2.0f * nx1);
                    const float n0 = (1.0f - e20) / (1.0f + e20);
                    const float n1 = (1.0f - e21) / (1.0f + e21);
                    float2 hn;
                    hn.x = (1.0f - z0) * n0 + z0 * hold.x;
                    hn.y = (1.0f - z1) * n1 + z1 * hold.y;
                    *reinterpret_cast<float2*>(hout + grow * 64 + c) = hn;
                }
            }
        }
        __syncthreads();
    }
}

// ---------------- gather propagated nodes into concat buffer ---------------
__global__ void gather_kernel(const int* __restrict__ prop0,
                              const int* __restrict__ prop1)
{
    const int i = blockIdx.x * blockDim.x + threadIdx.x;
    if (i >= 2 * BB * HH) return;
    const int half = i / (BB * HH);
    const int r    = i - half * (BB * HH);
    const int b = r >> 6, j = r & 63;
    const int node = half ? (prop1[b] + NN) : prop0[b];
    g_cat[b * 128 + half * 64 + j] = g_h0[(size_t)node * 64 + j];
}

// ---------------- hidden = relu(cat @ W1 + b1) -----------------------------
__global__ __launch_bounds__(256) void hidden_kernel(
    const float* __restrict__ W1, const float* __restrict__ b1)
{
    const int j   = threadIdx.x & 63;
    const int grp = threadIdx.x >> 6;
    float wc[2 * HH];
#pragma unroll
    for (int k = 0; k < 2 * HH; k++) wc[k] = W1[k * HH + j];
    const float bj = b1[j];

    __shared__ __align__(16) float s_c[4][2 * HH];
    const int ntiles = BB / 4;
    for (int tile = blockIdx.x; tile < ntiles; tile += gridDim.x) {
        const int b = tile * 4 + grp;
        __syncthreads();
        s_c[grp][j]      = g_cat[b * 128 + j];
        s_c[grp][j + 64] = g_cat[b * 128 + j + 64];
        __syncthreads();
        float a0 = bj, a1 = 0.0f;
#pragma unroll
        for (int k = 0; k < 2 * HH; k += 8) {
            const float4 v = *reinterpret_cast<const float4*>(&s_c[grp][k]);
            const float4 w = *reinterpret_cast<const float4*>(&s_c[grp][k + 4]);
            a0 = fmaf(v.x, wc[k + 0], a0);
            a1 = fmaf(v.y, wc[k + 1], a1);
            a0 = fmaf(v.z, wc[k + 2], a0);
            a1 = fmaf(v.w, wc[k + 3], a1);
            a0 = fmaf(w.x, wc[k + 4], a0);
            a1 = fmaf(w.y, wc[k + 5], a1);
            a0 = fmaf(w.z, wc[k + 6], a0);
            a1 = fmaf(w.w, wc[k + 7], a1);
        }
        g_hid[b * HH + j] = fmaxf(a0 + a1, 0.0f);
    }
}

// ---------------- head: z, probs, loss -------------------------------------
__global__ void head_kernel(const float* __restrict__ W2, const float* __restrict__ b2,
                            const int* __restrict__ labels, float* __restrict__ out)
{
    const int warp = (blockIdx.x * blockDim.x + threadIdx.x) >> 5;
    const int lane = threadIdx.x & 31;
    if (warp >= BB) return;
    float acc = fmaf(g_hid[warp * HH + lane],      W2[lane],      0.0f);
    acc       = fmaf(g_hid[warp * HH + lane + 32], W2[lane + 32], acc);
#pragma unroll
    for (int s = 16; s; s >>= 1) acc += __shfl_xor_sync(0xffffffffu, acc, s);
    if (lane == 0) {
        const float z = acc + b2[0];
        out[warp] = 1.0f / (1.0f + __expf(-z));
        const float y = (float)labels[warp];
        const float t = (y > 0.5f) ? -z : z;
        const float sp = fmaxf(t, 0.0f) + log1pf(__expf(-fabsf(t)));
        atomicAdd(&g_loss, sp);
    }
}

__global__ void finalize_kernel(float* __restrict__ out)
{
    out[BB] = g_loss * (1.0f / (float)BB);
}

// ---------------------------------------------------------------------------
extern "C" void kernel_launch(void* const* d_in, const int* in_sizes, int n_in,
                              void* d_out, int out_size)
{
    const int*   emb_ind[2] = {(const int*)d_in[0],  (const int*)d_in[1]};
    const int*   adj[2]     = {(const int*)d_in[2],  (const int*)d_in[3]};
    const int*   prop[2]    = {(const int*)d_in[4],  (const int*)d_in[5]};
    const int*   labels     =  (const int*)d_in[6];
    const float* emb_table  =  (const float*)d_in[7];
    const float* Wp         =  (const float*)d_in[8];
    const float* bp         =  (const float*)d_in[9];
    const float* Wm[2]  = {(const float*)d_in[10], (const float*)d_in[16]};
    const float* bm[2]  = {(const float*)d_in[11], (const float*)d_in[17]};
    const float* Wih[2] = {(const float*)d_in[12], (const float*)d_in[18]};
    const float* Whh[2] = {(const float*)d_in[13], (const float*)d_in[19]};
    const float* bih[2] = {(const float*)d_in[14], (const float*)d_in[20]};
    const float* bhh[2] = {(const float*)d_in[15], (const float*)d_in[21]};
    const float* W1 = (const float*)d_in[22];
    const float* b1 = (const float*)d_in[23];
    const float* W2 = (const float*)d_in[24];
    const float* b2 = (const float*)d_in[25];
    float* out = (float*)d_out;

    static bool attr_set = false;
    if (!attr_set) {
        cudaFuncSetAttribute(gg2_kernel,
                             cudaFuncAttributeMaxDynamicSharedMemorySize, SM_TOTAL);
        cudaFuncSetAttribute(proj_mma_kernel,
                             cudaFuncAttributeMaxDynamicSharedMemorySize, PSM_TOTAL);
        attr_set = true;
    }

    init_kernel<<<(NPAD + 255) / 256, 256>>>();
    deg_kernel<<<(E2 + 255) / 256, 256>>>(adj[0], adj[1]);
    scan1_kernel<<<SCAN_B, 256>>>();
    scan2_kernel<<<1, 1024>>>();
    scan3_kernel<<<SCAN_B, 256>>>();
    fill_kernel<<<(E2 + 255) / 256, 256>>>(adj[0], adj[1]);
    {
        dim3 fg(HH + 1, 2);
        fuse1_kernel<<<fg, 192>>>(Wm[0], Wih[0], bm[0], Wm[1], Wih[1], bm[1]);
    }
    {
        dim3 f2(256, 2);
        fuse2_kernel<<<f2, 128>>>(Whh[0], Whh[1]);
    }
    proj_mma_kernel<<<GGRID, 256, PSM_TOTAL>>>(emb_table, emb_ind[0], emb_ind[1], Wp, bp);
    int step = 0;
    for (int l = 0; l < 2; l++) {
        for (int t = 0; t < 3; t++) {
            gg2_kernel<<<GGRID, 256, SM_TOTAL>>>(bih[l], bhh[l], l, step & 1);
            step++;
        }
    }
    gather_kernel<<<(2 * BB * HH + 255) / 256, 256>>>(prop[0], prop[1]);
    hidden_kernel<<<512, 256>>>(W1, b1);
    head_kernel<<<(BB * 32 + 255) / 256, 256>>>(W2, b2, labels, out);
    finalize_kernel<<<1, 1>>>(out);
    (void)in_sizes; (void)n_in; (void)out_size;
}